// round 13
// baseline (speedup 1.0000x reference)
#include <cuda_runtime.h>
#include <cuda_bf16.h>
#include <cstdint>

// ---------------- problem constants ----------------
#define BB   256
#define DD_  512
#define TT   256
#define NDD  (DD_ * DD_)     // 262144
#define NBD  (BB * DD_)      // 131072

#define THREADS 256
#define SMEM_ALL 98304       // all kernels: small KC64 NBUF3 = fine KC32 NBUF3 = 96KB

// ---------------- pre-split bf16 hi/lo global matrices ----------------
static __device__ __align__(16) uint16_t gPh [34 * NDD];
static __device__ __align__(16) uint16_t gPl [34 * NDD];
static __device__ __align__(16) uint16_t gPTh[34 * NDD];
static __device__ __align__(16) uint16_t gPTl[34 * NDD];
static __device__ __align__(16) uint16_t gAh [8 * NBD];
static __device__ __align__(16) uint16_t gAl [8 * NBD];

static __device__ __forceinline__ uint16_t* Ph (int j) { return gPh  + (size_t)(j - 1) * NDD; }
static __device__ __forceinline__ uint16_t* Pl (int j) { return gPl  + (size_t)(j - 1) * NDD; }
static __device__ __forceinline__ uint16_t* PTh(int j) { return gPTh + (size_t)(j - 1) * NDD; }
static __device__ __forceinline__ uint16_t* PTl(int j) { return gPTl + (size_t)(j - 1) * NDD; }

// ---------------- helpers ----------------
static __device__ __forceinline__ uint32_t smem_u32(const void* p) {
    uint32_t a;
    asm("{ .reg .u64 t; cvta.to.shared.u64 t, %1; cvt.u32.u64 %0, t; }" : "=r"(a) : "l"(p));
    return a;
}
static __device__ __forceinline__ uint32_t bf16x2_pack(float x0, float x1) {
    uint32_t d;
    asm("cvt.rn.bf16x2.f32 %0, %2, %1;" : "=r"(d) : "f"(x0), "f"(x1));
    return d;
}
static __device__ __forceinline__ float bf16_lo_f(uint32_t u) { return __uint_as_float(u << 16); }
static __device__ __forceinline__ float bf16_hi_f(uint32_t u) { return __uint_as_float(u & 0xFFFF0000u); }

#define LDSM4(r0, r1, r2, r3, addr) \
    asm volatile("ldmatrix.sync.aligned.m8n8.x4.shared.b16 {%0,%1,%2,%3}, [%4];" \
                 : "=r"(r0), "=r"(r1), "=r"(r2), "=r"(r3) : "r"(addr))

#define MMA16816(c, a, b0, b1) \
    asm volatile("mma.sync.aligned.m16n8k16.row.col.f32.bf16.bf16.f32 " \
                 "{%0,%1,%2,%3}, {%4,%5,%6,%7}, {%8,%9}, {%0,%1,%2,%3};" \
                 : "+f"((c)[0]), "+f"((c)[1]), "+f"((c)[2]), "+f"((c)[3]) \
                 : "r"((a)[0]), "r"((a)[1]), "r"((a)[2]), "r"((a)[3]), \
                   "r"(b0), "r"(b1))

#define CP16(dst, src) \
    asm volatile("cp.async.cg.shared.global [%0], [%1], 16;" :: "r"(dst), "l"(src))
#define CPCOMMIT() asm volatile("cp.async.commit_group;" ::: "memory")

// ---------------- TMv x TNv x 512 split-bf16 HMMA GEMM tile ----------------
// C[m][n] = sum_k (Ah+Al)[m][k]*(Bh+Bl)[n][k], lo*lo dropped. Outputs nullable.
// NB stage buffers, DP prefetch distance (NB == DP+1), KCv = k per stage.
template<int TMv, int TNv, int THR, int NB, int DP, int KCv>
static __device__ __forceinline__ void gemmt(
        const uint16_t* __restrict__ Ah, const uint16_t* __restrict__ Al,
        const uint16_t* __restrict__ Bh, const uint16_t* __restrict__ Bl,
        float* __restrict__ C, size_t cs,
        uint16_t* __restrict__ Ch, uint16_t* __restrict__ Cl,
        uint16_t* __restrict__ CTh, uint16_t* __restrict__ CTl,
        int m0, int n0) {
    static_assert(NB == DP + 1, "buffer schedule assumes NB == DP+1");
    constexpr int NST = DD_ / KCv;         // stages
    constexpr int NKK = KCv / 16;          // k16 chunks per stage
    constexpr int NCH = KCv / 8;           // 16B chunks per row
    constexpr int RWB = KCv * 2;           // row bytes
    constexpr int NWM = TMv / 32;
    constexpr int NWN = (THR / 32) / NWM;
    constexpr int WN  = TNv / NWN;
    constexpr int NF  = WN / 8;
    constexpr int NQ  = WN / 16;
    constexpr int AMB = TMv * RWB;
    constexpr int BMB = TNv * RWB;
    constexpr int STG = 2 * AMB + 2 * BMB;

    extern __shared__ char smem[];
    const uint32_t sb = smem_u32(smem);
    const int tid = threadIdx.x;
    const int wid = tid >> 5, l = tid & 31;
    const int wm = (wid / NWN) * 32;
    const int wn = (wid % NWN) * WN;

    // swizzle: XOR 16B-chunk bits with row LSBs (64B rows: 2 bits; 128B rows: 3 bits)
    auto swz = [](uint32_t off) -> uint32_t {
        return KCv == 32 ? (off ^ ((off >> 3) & 0x30u))
                         : (off ^ ((off >> 3) & 0x70u));
    };

    float c[2][NF][4];
#pragma unroll
    for (int i = 0; i < 2; ++i)
#pragma unroll
        for (int j = 0; j < NF; ++j)
#pragma unroll
            for (int q = 0; q < 4; ++q) c[i][j][q] = 0.0f;

    const uint32_t a_row = (uint32_t)(wm + (l & 15));
    const uint32_t a_ch  = (uint32_t)(l >> 4);
    const uint32_t b_row = (uint32_t)(wn + (l & 7) + ((l & 16) >> 1));
    const uint32_t b_ch  = (uint32_t)((l >> 3) & 1);

    auto issue = [&](int s) {
        const uint32_t bufb = sb + (uint32_t)(s % NB) * STG;
        const int ko = s * KCv;
#pragma unroll
        for (int i = tid; i < TMv * NCH; i += THR) {
            const int row = i / NCH, ch = i % NCH;
            const uint32_t d = bufb + swz((uint32_t)(row * RWB + ch * 16));
            const size_t g = (size_t)(m0 + row) * DD_ + ko + ch * 8;
            CP16(d,       Ah + g);
            CP16(d + AMB, Al + g);
        }
#pragma unroll
        for (int i = tid; i < TNv * NCH; i += THR) {
            const int row = i / NCH, ch = i % NCH;
            const uint32_t d = bufb + 2 * AMB + swz((uint32_t)(row * RWB + ch * 16));
            const size_t g = (size_t)(n0 + row) * DD_ + ko + ch * 8;
            CP16(d,       Bh + g);
            CP16(d + BMB, Bl + g);
        }
    };

#pragma unroll
    for (int s = 0; s < DP; ++s) { issue(s); CPCOMMIT(); }

    for (int s = 0; s < NST; ++s) {
        asm volatile("cp.async.wait_group %0;" :: "n"(DP - 1) : "memory");
        __syncthreads();

        // early issue: target buffer (s+DP)%NB == (s-1)%NB, drained before barrier
        if (s + DP < NST) issue(s + DP);
        CPCOMMIT();

        const uint32_t base = sb + (uint32_t)(s % NB) * STG;
        const uint32_t sA  = base;
        const uint32_t sAl = base + AMB;
        const uint32_t sB  = base + 2 * AMB;
        const uint32_t sBl = base + 2 * AMB + BMB;

#pragma unroll
        for (int kk = 0; kk < NKK; ++kk) {
            uint32_t ah[2][4], al[2][4], bh[NQ][4], bl[NQ][4];
            const uint32_t ach = (uint32_t)(2 * kk) + a_ch;
            const uint32_t bch = (uint32_t)(2 * kk) + b_ch;
#pragma unroll
            for (int mf = 0; mf < 2; ++mf) {
                const uint32_t off = swz((a_row + mf * 16) * RWB + ach * 16);
                LDSM4(ah[mf][0], ah[mf][1], ah[mf][2], ah[mf][3], sA + off);
                LDSM4(al[mf][0], al[mf][1], al[mf][2], al[mf][3], sAl + off);
            }
#pragma unroll
            for (int q = 0; q < NQ; ++q) {
                const uint32_t off = swz((b_row + q * 16) * RWB + bch * 16);
                LDSM4(bh[q][0], bh[q][1], bh[q][2], bh[q][3], sB + off);
                LDSM4(bl[q][0], bl[q][1], bl[q][2], bl[q][3], sBl + off);
            }
#pragma unroll
            for (int mf = 0; mf < 2; ++mf)
#pragma unroll
                for (int nf = 0; nf < NF; ++nf) {
                    const int q = nf >> 1, hh = (nf & 1) * 2;
                    MMA16816(c[mf][nf], ah[mf], bh[q][hh], bh[q][hh + 1]);
                    MMA16816(c[mf][nf], ah[mf], bl[q][hh], bl[q][hh + 1]);
                    MMA16816(c[mf][nf], al[mf], bh[q][hh], bh[q][hh + 1]);
                }
        }
    }

    // ---------------- epilogue ----------------
    const int row0 = m0 + wm + (l >> 2);
    const int col0 = n0 + wn + 2 * (l & 3);
#pragma unroll
    for (int mf = 0; mf < 2; ++mf)
#pragma unroll
        for (int nf = 0; nf < NF; ++nf) {
            const int rr = row0 + mf * 16;
            const int cc = col0 + nf * 8;
            const float v0 = c[mf][nf][0], v1 = c[mf][nf][1];
            const float v2 = c[mf][nf][2], v3 = c[mf][nf][3];
            if (C) {
                *(float2*)(C + (size_t)rr * cs + cc)       = make_float2(v0, v1);
                *(float2*)(C + (size_t)(rr + 8) * cs + cc) = make_float2(v2, v3);
            }
            if (Ch) {
                uint32_t p01 = bf16x2_pack(v0, v1);
                uint32_t p23 = bf16x2_pack(v2, v3);
                uint32_t q01 = bf16x2_pack(v0 - bf16_lo_f(p01), v1 - bf16_hi_f(p01));
                uint32_t q23 = bf16x2_pack(v2 - bf16_lo_f(p23), v3 - bf16_hi_f(p23));
                *(uint32_t*)(Ch + (size_t)rr * DD_ + cc)       = p01;
                *(uint32_t*)(Cl + (size_t)rr * DD_ + cc)       = q01;
                *(uint32_t*)(Ch + (size_t)(rr + 8) * DD_ + cc) = p23;
                *(uint32_t*)(Cl + (size_t)(rr + 8) * DD_ + cc) = q23;
                if (CTh) {
                    CTh[(size_t)cc * DD_ + rr]           = (uint16_t)p01;
                    CTh[(size_t)(cc + 1) * DD_ + rr]     = (uint16_t)(p01 >> 16);
                    CTh[(size_t)cc * DD_ + rr + 8]       = (uint16_t)p23;
                    CTh[(size_t)(cc + 1) * DD_ + rr + 8] = (uint16_t)(p23 >> 16);
                    CTl[(size_t)cc * DD_ + rr]           = (uint16_t)q01;
                    CTl[(size_t)(cc + 1) * DD_ + rr]     = (uint16_t)(q01 >> 16);
                    CTl[(size_t)cc * DD_ + rr + 8]       = (uint16_t)q23;
                    CTl[(size_t)(cc + 1) * DD_ + rr + 8] = (uint16_t)(q23 >> 16);
                }
            }
        }
}

// small 64x64 tiles: KC=64 (8 stages), NBUF=3 -> 96KB, 2 CTA/SM
#define SMALL_GEMM gemmt<64, 64, THREADS, 3, 2, 64>
// fine 128x128 tiles: KC=32 (16 stages), NBUF=3 -> 96KB, 2 CTA/SM
#define FINE_GEMM  gemmt<128, 128, THREADS, 3, 2, 32>

// helper: run one fine tile for timestep t, subtile sub (0..7)
static __device__ __forceinline__ void fine_tile(float* __restrict__ out, int t, int sub) {
    FINE_GEMM(gAh + (size_t)(t >> 5) * NBD, gAl + (size_t)(t >> 5) * NBD,
              PTh((t & 31) + 1), PTl((t & 31) + 1),
              out + (size_t)t * DD_, (size_t)TT * DD_,
              nullptr, nullptr, nullptr, nullptr,
              ((sub >> 2) & 1) * 128, (sub & 3) * 128);
}

// ---------------- kernels ----------------

// seed: split K -> slot1 (row-major + transposed), z0 -> anchor 0
__global__ void __launch_bounds__(512) k_seed(const float* __restrict__ K,
                                              const float* __restrict__ z0) {
    int i = blockIdx.x * blockDim.x + threadIdx.x;
    if (i < NDD) {
        float v = K[i];
        uint32_t p = bf16x2_pack(v, v);
        uint16_t hp = (uint16_t)p;
        uint16_t lp = (uint16_t)bf16x2_pack(v - bf16_lo_f(p), 0.0f);
        int r = i >> 9, cc = i & 511;
        gPh[i] = hp;  gPl[i] = lp;
        gPTh[(size_t)cc * DD_ + r] = hp;
        gPTl[(size_t)cc * DD_ + r] = lp;
    } else {
        int j = i - NDD;
        float v = z0[j];
        uint32_t p = bf16x2_pack(v, v);
        gAh[j] = (uint16_t)p;
        gAl[j] = (uint16_t)bf16x2_pack(v - bf16_lo_f(p), 0.0f);
    }
}

// powers doubling: for z in [0,base): P_{base+z+1} = P_base @ P_{z+1}
__global__ void __launch_bounds__(THREADS, 2) k_power(int base) {
    int z = blockIdx.z;
    int dst = base + z + 1;
    SMALL_GEMM(Ph(base), Pl(base), PTh(z + 1), PTl(z + 1),
               nullptr, 0, Ph(dst), Pl(dst), PTh(dst), PTl(dst),
               blockIdx.y * 64, blockIdx.x * 64);
}

// mix7: K^64 (64 tiles) + a1 = a0 @ K^32 (32 tiles) + fine t=0..31 (256 tiles) = 352
__global__ void __launch_bounds__(THREADS, 2) k_mix7(float* __restrict__ out) {
    int i = blockIdx.x;
    if (i < 64) {
        SMALL_GEMM(Ph(32), Pl(32), PTh(32), PTl(32),
                   nullptr, 0, Ph(33), Pl(33), PTh(33), PTl(33),
                   (i >> 3) * 64, (i & 7) * 64);
    } else if (i < 96) {
        int r = i - 64;
        SMALL_GEMM(gAh, gAl, PTh(32), PTl(32),
                   nullptr, 0, gAh + NBD, gAl + NBD, nullptr, nullptr,
                   (r >> 3) * 64, (r & 7) * 64);
    } else {
        int f = i - 96;
        fine_tile(out, f >> 3, f & 7);
    }
}

// mix8: K^128 (64) + a2 = a0@K^64 (32) + a3 = a1@K^64 (32) + fine t=32..52 (168) = 296
__global__ void __launch_bounds__(THREADS, 2) k_mix8(float* __restrict__ out) {
    int i = blockIdx.x;
    if (i < 64) {
        SMALL_GEMM(Ph(33), Pl(33), PTh(33), PTl(33),
                   nullptr, 0, Ph(34), Pl(34), PTh(34), PTl(34),
                   (i >> 3) * 64, (i & 7) * 64);
    } else if (i < 128) {
        int r = i - 64;              // 0..63
        int a = r >> 5;              // 0 -> a2 (from a0), 1 -> a3 (from a1)
        int rr = r & 31;
        SMALL_GEMM(gAh + (size_t)a * NBD, gAl + (size_t)a * NBD, PTh(33), PTl(33),
                   nullptr, 0, gAh + (size_t)(a + 2) * NBD, gAl + (size_t)(a + 2) * NBD,
                   nullptr, nullptr, (rr >> 3) * 64, (rr & 7) * 64);
    } else {
        int f = i - 128;
        fine_tile(out, 32 + (f >> 3), f & 7);
    }
}

// mix9: a_{4+z} = a_z @ K^128, z=0..3 (128) + fine t=53..73 (168) = 296
__global__ void __launch_bounds__(THREADS, 2) k_mix9(float* __restrict__ out) {
    int i = blockIdx.x;
    if (i < 128) {
        int z = i >> 5, rr = i & 31;
        SMALL_GEMM(gAh + (size_t)z * NBD, gAl + (size_t)z * NBD, PTh(34), PTl(34),
                   nullptr, 0, gAh + (size_t)(z + 4) * NBD, gAl + (size_t)(z + 4) * NBD,
                   nullptr, nullptr, (rr >> 3) * 64, (rr & 7) * 64);
    } else {
        int f = i - 128;
        fine_tile(out, 53 + (f >> 3), f & 7);
    }
}

// fine2: t = 74..255 (182 t x 8 tiles = 1456 CTAs)
__global__ void __launch_bounds__(THREADS, 2) k_fine2(float* __restrict__ out) {
    fine_tile(out, 74 + (int)(blockIdx.x >> 3), (int)(blockIdx.x & 7));
}

// ---------------- launch ----------------
extern "C" void kernel_launch(void* const* d_in, const int* in_sizes, int n_in,
                              void* d_out, int out_size) {
    const float* z0 = (const float*)d_in[0];
    const float* K  = (const float*)d_in[1];
    float* out = (float*)d_out;

    cudaFuncSetAttribute(k_power, cudaFuncAttributeMaxDynamicSharedMemorySize, SMEM_ALL);
    cudaFuncSetAttribute(k_mix7,  cudaFuncAttributeMaxDynamicSharedMemorySize, SMEM_ALL);
    cudaFuncSetAttribute(k_mix8,  cudaFuncAttributeMaxDynamicSharedMemorySize, SMEM_ALL);
    cudaFuncSetAttribute(k_mix9,  cudaFuncAttributeMaxDynamicSharedMemorySize, SMEM_ALL);
    cudaFuncSetAttribute(k_fine2, cudaFuncAttributeMaxDynamicSharedMemorySize, SMEM_ALL);

    k_seed<<<(NDD + NBD) / 512, 512>>>(K, z0);

    for (int base = 1; base <= 16; base *= 2)
        k_power<<<dim3(8, 8, base), THREADS, SMEM_ALL>>>(base);

    k_mix7<<<352, THREADS, SMEM_ALL>>>(out);
    k_mix8<<<296, THREADS, SMEM_ALL>>>(out);
    k_mix9<<<296, THREADS, SMEM_ALL>>>(out);
    k_fine2<<<1456, THREADS, SMEM_ALL>>>(out);
}

// round 14
// speedup vs baseline: 1.0474x; 1.0474x over previous
#include <cuda_runtime.h>
#include <cuda_bf16.h>
#include <cstdint>

// ---------------- problem constants ----------------
#define BB   256
#define DD_  512
#define TT   256
#define NDD  (DD_ * DD_)     // 262144
#define NBD  (BB * DD_)      // 131072

#define KC   32              // k per stage
#define NSTG (DD_ / KC)      // 16 stages (fine)
#define GS   256             // k per split-k group (small)
#define NSTG_SK (GS / KC)    // 8 stages per group

#define SMEM_ALL 98304       // fine: 3 x 32KB; small: 3 x 2 x 16KB

// ---------------- pre-split bf16 hi/lo global matrices ----------------
static __device__ __align__(16) uint16_t gPh [34 * NDD];
static __device__ __align__(16) uint16_t gPl [34 * NDD];
static __device__ __align__(16) uint16_t gPTh[34 * NDD];
static __device__ __align__(16) uint16_t gPTl[34 * NDD];
static __device__ __align__(16) uint16_t gAh [8 * NBD];
static __device__ __align__(16) uint16_t gAl [8 * NBD];

static __device__ __forceinline__ uint16_t* Ph (int j) { return gPh  + (size_t)(j - 1) * NDD; }
static __device__ __forceinline__ uint16_t* Pl (int j) { return gPl  + (size_t)(j - 1) * NDD; }
static __device__ __forceinline__ uint16_t* PTh(int j) { return gPTh + (size_t)(j - 1) * NDD; }
static __device__ __forceinline__ uint16_t* PTl(int j) { return gPTl + (size_t)(j - 1) * NDD; }

// ---------------- helpers ----------------
static __device__ __forceinline__ uint32_t smem_u32(const void* p) {
    uint32_t a;
    asm("{ .reg .u64 t; cvta.to.shared.u64 t, %1; cvt.u32.u64 %0, t; }" : "=r"(a) : "l"(p));
    return a;
}
static __device__ __forceinline__ uint32_t bf16x2_pack(float x0, float x1) {
    uint32_t d;
    asm("cvt.rn.bf16x2.f32 %0, %2, %1;" : "=r"(d) : "f"(x0), "f"(x1));
    return d;
}
static __device__ __forceinline__ float bf16_lo_f(uint32_t u) { return __uint_as_float(u << 16); }
static __device__ __forceinline__ float bf16_hi_f(uint32_t u) { return __uint_as_float(u & 0xFFFF0000u); }

// swizzle for 64B rows: XOR 16B-chunk bits [5:4] with row bits [2:1]
static __device__ __forceinline__ uint32_t swz64(uint32_t off) {
    return off ^ ((off >> 3) & 0x30u);
}

#define LDSM4(r0, r1, r2, r3, addr) \
    asm volatile("ldmatrix.sync.aligned.m8n8.x4.shared.b16 {%0,%1,%2,%3}, [%4];" \
                 : "=r"(r0), "=r"(r1), "=r"(r2), "=r"(r3) : "r"(addr))

#define MMA16816(c, a, b0, b1) \
    asm volatile("mma.sync.aligned.m16n8k16.row.col.f32.bf16.bf16.f32 " \
                 "{%0,%1,%2,%3}, {%4,%5,%6,%7}, {%8,%9}, {%0,%1,%2,%3};" \
                 : "+f"((c)[0]), "+f"((c)[1]), "+f"((c)[2]), "+f"((c)[3]) \
                 : "r"((a)[0]), "r"((a)[1]), "r"((a)[2]), "r"((a)[3]), \
                   "r"(b0), "r"(b1))

#define CP16(dst, src) \
    asm volatile("cp.async.cg.shared.global [%0], [%1], 16;" :: "r"(dst), "l"(src))
#define CPCOMMIT() asm volatile("cp.async.commit_group;" ::: "memory")
#define CPWAIT(n)  asm volatile("cp.async.wait_group %0;" :: "n"(n) : "memory")

// ---------------- fine GEMM: 128x128x512, 256 thr, NBUF=3, DP=2 (R12-exact) ----------------
static __device__ __forceinline__ void gemm_fine(
        const uint16_t* __restrict__ Ah, const uint16_t* __restrict__ Al,
        const uint16_t* __restrict__ Bh, const uint16_t* __restrict__ Bl,
        float* __restrict__ C, size_t cs, int m0, int n0) {
    constexpr int AMB = 128 * 64;
    constexpr int BMB = 128 * 64;
    constexpr int STG = 2 * AMB + 2 * BMB;   // 32KB

    extern __shared__ char smem[];
    const uint32_t sb = smem_u32(smem);
    const int tid = threadIdx.x;
    const int wid = tid >> 5, l = tid & 31;
    const int wm = (wid >> 1) * 32;          // NWM=4
    const int wn = (wid & 1) * 64;           // NWN=2, WN=64, NF=8, NQ=4

    float c[2][8][4];
#pragma unroll
    for (int i = 0; i < 2; ++i)
#pragma unroll
        for (int j = 0; j < 8; ++j)
#pragma unroll
            for (int q = 0; q < 4; ++q) c[i][j][q] = 0.0f;

    const uint32_t a_row = (uint32_t)(wm + (l & 15));
    const uint32_t a_ch  = (uint32_t)(l >> 4);
    const uint32_t b_row = (uint32_t)(wn + (l & 7) + ((l & 16) >> 1));
    const uint32_t b_ch  = (uint32_t)((l >> 3) & 1);

    auto issue = [&](int s) {
        const uint32_t bufb = sb + (uint32_t)(s % 3) * STG;
        const int ko = s * KC;
#pragma unroll
        for (int i = tid; i < 128 * 4; i += 256) {
            const int row = i >> 2, ch = i & 3;
            const uint32_t d = bufb + swz64((uint32_t)(row * 64 + ch * 16));
            const size_t g = (size_t)(m0 + row) * DD_ + ko + ch * 8;
            CP16(d,       Ah + g);
            CP16(d + AMB, Al + g);
        }
#pragma unroll
        for (int i = tid; i < 128 * 4; i += 256) {
            const int row = i >> 2, ch = i & 3;
            const uint32_t d = bufb + 2 * AMB + swz64((uint32_t)(row * 64 + ch * 16));
            const size_t g = (size_t)(n0 + row) * DD_ + ko + ch * 8;
            CP16(d,       Bh + g);
            CP16(d + BMB, Bl + g);
        }
    };

    issue(0); CPCOMMIT();
    issue(1); CPCOMMIT();

    for (int s = 0; s < NSTG; ++s) {
        CPWAIT(1);
        __syncthreads();

        const uint32_t base = sb + (uint32_t)(s % 3) * STG;
        const uint32_t sA  = base;
        const uint32_t sAl = base + AMB;
        const uint32_t sB  = base + 2 * AMB;
        const uint32_t sBl = base + 2 * AMB + BMB;

#pragma unroll
        for (int kk = 0; kk < 2; ++kk) {
            uint32_t ah[2][4], al[2][4], bh[4][4], bl[4][4];
            const uint32_t ach = (uint32_t)(2 * kk) + a_ch;
            const uint32_t bch = (uint32_t)(2 * kk) + b_ch;
#pragma unroll
            for (int mf = 0; mf < 2; ++mf) {
                const uint32_t off = swz64((a_row + mf * 16) * 64 + ach * 16);
                LDSM4(ah[mf][0], ah[mf][1], ah[mf][2], ah[mf][3], sA + off);
                LDSM4(al[mf][0], al[mf][1], al[mf][2], al[mf][3], sAl + off);
            }
#pragma unroll
            for (int q = 0; q < 4; ++q) {
                const uint32_t off = swz64((b_row + q * 16) * 64 + bch * 16);
                LDSM4(bh[q][0], bh[q][1], bh[q][2], bh[q][3], sB + off);
                LDSM4(bl[q][0], bl[q][1], bl[q][2], bl[q][3], sBl + off);
            }
#pragma unroll
            for (int mf = 0; mf < 2; ++mf)
#pragma unroll
                for (int nf = 0; nf < 8; ++nf) {
                    const int q = nf >> 1, hh = (nf & 1) * 2;
                    MMA16816(c[mf][nf], ah[mf], bh[q][hh], bh[q][hh + 1]);
                    MMA16816(c[mf][nf], ah[mf], bl[q][hh], bl[q][hh + 1]);
                    MMA16816(c[mf][nf], al[mf], bh[q][hh], bh[q][hh + 1]);
                }
        }
        if (s + 2 < NSTG) issue(s + 2);
        CPCOMMIT();
    }

    const int row0 = m0 + wm + (l >> 2);
    const int col0 = n0 + wn + 2 * (l & 3);
#pragma unroll
    for (int mf = 0; mf < 2; ++mf)
#pragma unroll
        for (int nf = 0; nf < 8; ++nf) {
            const int rr = row0 + mf * 16;
            const int cc = col0 + nf * 8;
            *(float2*)(C + (size_t)rr * cs + cc)       = make_float2(c[mf][nf][0], c[mf][nf][1]);
            *(float2*)(C + (size_t)(rr + 8) * cs + cc) = make_float2(c[mf][nf][2], c[mf][nf][3]);
        }
}

// ---------------- small GEMM: 64x64x512, 512 thr, intra-CTA split-k=2 ----------------
// Warp-group g (8 warps) accumulates k in [g*256, g*256+256); group 1 dumps fp32
// partials to smem; group 0 adds and runs the split/transpose epilogue.
static __device__ __forceinline__ void gemm_sk(
        const uint16_t* __restrict__ Ah, const uint16_t* __restrict__ Al,
        const uint16_t* __restrict__ Bh, const uint16_t* __restrict__ Bl,
        uint16_t* __restrict__ Ch, uint16_t* __restrict__ Cl,
        uint16_t* __restrict__ CTh, uint16_t* __restrict__ CTl,
        int m0, int n0) {
    constexpr int AMB = 64 * 64;             // 4KB per half-matrix
    constexpr int BMB = 64 * 64;
    constexpr int STG = 2 * AMB + 2 * BMB;   // 16KB per group-stage

    extern __shared__ char smem[];
    const uint32_t sb = smem_u32(smem);
    const int tid = threadIdx.x;
    const int g = tid >> 8;                  // k-group 0/1
    const int wg = tid & 255;
    const int wid = wg >> 5, l = wg & 31;
    const int wm = (wid >> 2) * 32;          // NWM=2
    const int wn = (wid & 3) * 16;           // NWN=4, WN=16, NF=2, NQ=1
    const int kbase = g * GS;

    float c[2][2][4];
#pragma unroll
    for (int i = 0; i < 2; ++i)
#pragma unroll
        for (int j = 0; j < 2; ++j)
#pragma unroll
            for (int q = 0; q < 4; ++q) c[i][j][q] = 0.0f;

    const uint32_t a_row = (uint32_t)(wm + (l & 15));
    const uint32_t a_ch  = (uint32_t)(l >> 4);
    const uint32_t b_row = (uint32_t)(wn + (l & 7) + ((l & 16) >> 1));
    const uint32_t b_ch  = (uint32_t)((l >> 3) & 1);

    auto issue = [&](int s) {
        const uint32_t bufb = sb + (uint32_t)((s % 3) * 2 + g) * STG;
        const int ko = kbase + s * KC;
        {   // A: 64 rows x 4 chunks = 256 slots, one per group thread
            const int row = wg >> 2, ch = wg & 3;
            const uint32_t d = bufb + swz64((uint32_t)(row * 64 + ch * 16));
            const size_t ga = (size_t)(m0 + row) * DD_ + ko + ch * 8;
            CP16(d,       Ah + ga);
            CP16(d + AMB, Al + ga);
            const uint32_t db = bufb + 2 * AMB + swz64((uint32_t)(row * 64 + ch * 16));
            const size_t gb = (size_t)(n0 + row) * DD_ + ko + ch * 8;
            CP16(db,       Bh + gb);
            CP16(db + BMB, Bl + gb);
        }
    };

    issue(0); CPCOMMIT();
    issue(1); CPCOMMIT();

    for (int s = 0; s < NSTG_SK; ++s) {
        CPWAIT(1);
        __syncthreads();

        const uint32_t base = sb + (uint32_t)((s % 3) * 2 + g) * STG;
        const uint32_t sA  = base;
        const uint32_t sAl = base + AMB;
        const uint32_t sB  = base + 2 * AMB;
        const uint32_t sBl = base + 2 * AMB + BMB;

#pragma unroll
        for (int kk = 0; kk < 2; ++kk) {
            uint32_t ah[2][4], al[2][4], bh[4], bl[4];
            const uint32_t ach = (uint32_t)(2 * kk) + a_ch;
            const uint32_t bch = (uint32_t)(2 * kk) + b_ch;
#pragma unroll
            for (int mf = 0; mf < 2; ++mf) {
                const uint32_t off = swz64((a_row + mf * 16) * 64 + ach * 16);
                LDSM4(ah[mf][0], ah[mf][1], ah[mf][2], ah[mf][3], sA + off);
                LDSM4(al[mf][0], al[mf][1], al[mf][2], al[mf][3], sAl + off);
            }
            {
                const uint32_t off = swz64(b_row * 64 + bch * 16);
                LDSM4(bh[0], bh[1], bh[2], bh[3], sB + off);
                LDSM4(bl[0], bl[1], bl[2], bl[3], sBl + off);
            }
#pragma unroll
            for (int mf = 0; mf < 2; ++mf)
#pragma unroll
                for (int nf = 0; nf < 2; ++nf) {
                    const int hh = nf * 2;
                    MMA16816(c[mf][nf], ah[mf], bh[hh], bh[hh + 1]);
                    MMA16816(c[mf][nf], ah[mf], bl[hh], bl[hh + 1]);
                    MMA16816(c[mf][nf], al[mf], bh[hh], bh[hh + 1]);
                }
        }
        if (s + 2 < NSTG_SK) issue(s + 2);
        CPCOMMIT();
    }

    // ---------------- split-k reduction ----------------
    CPWAIT(0);             // drain pending loads before reusing buffer smem
    __syncthreads();
    float* red = (float*)smem;               // 256 threads x 16 floats = 16KB
    if (g == 1) {
#pragma unroll
        for (int i = 0; i < 2; ++i)
#pragma unroll
            for (int j = 0; j < 2; ++j)
                *(float4*)(red + (wg * 16 + (i * 2 + j) * 4)) =
                    make_float4(c[i][j][0], c[i][j][1], c[i][j][2], c[i][j][3]);
    }
    __syncthreads();
    if (g != 0) return;
#pragma unroll
    for (int i = 0; i < 2; ++i)
#pragma unroll
        for (int j = 0; j < 2; ++j) {
            float4 v = *(float4*)(red + (wg * 16 + (i * 2 + j) * 4));
            c[i][j][0] += v.x; c[i][j][1] += v.y;
            c[i][j][2] += v.z; c[i][j][3] += v.w;
        }

    // ---------------- epilogue (group 0 only) ----------------
    const int row0 = m0 + wm + (l >> 2);
    const int col0 = n0 + wn + 2 * (l & 3);
#pragma unroll
    for (int mf = 0; mf < 2; ++mf)
#pragma unroll
        for (int nf = 0; nf < 2; ++nf) {
            const int rr = row0 + mf * 16;
            const int cc = col0 + nf * 8;
            const float v0 = c[mf][nf][0], v1 = c[mf][nf][1];
            const float v2 = c[mf][nf][2], v3 = c[mf][nf][3];
            uint32_t p01 = bf16x2_pack(v0, v1);
            uint32_t p23 = bf16x2_pack(v2, v3);
            uint32_t q01 = bf16x2_pack(v0 - bf16_lo_f(p01), v1 - bf16_hi_f(p01));
            uint32_t q23 = bf16x2_pack(v2 - bf16_lo_f(p23), v3 - bf16_hi_f(p23));
            *(uint32_t*)(Ch + (size_t)rr * DD_ + cc)       = p01;
            *(uint32_t*)(Cl + (size_t)rr * DD_ + cc)       = q01;
            *(uint32_t*)(Ch + (size_t)(rr + 8) * DD_ + cc) = p23;
            *(uint32_t*)(Cl + (size_t)(rr + 8) * DD_ + cc) = q23;
            if (CTh) {
                CTh[(size_t)cc * DD_ + rr]           = (uint16_t)p01;
                CTh[(size_t)(cc + 1) * DD_ + rr]     = (uint16_t)(p01 >> 16);
                CTh[(size_t)cc * DD_ + rr + 8]       = (uint16_t)p23;
                CTh[(size_t)(cc + 1) * DD_ + rr + 8] = (uint16_t)(p23 >> 16);
                CTl[(size_t)cc * DD_ + rr]           = (uint16_t)q01;
                CTl[(size_t)(cc + 1) * DD_ + rr]     = (uint16_t)(q01 >> 16);
                CTl[(size_t)cc * DD_ + rr + 8]       = (uint16_t)q23;
                CTl[(size_t)(cc + 1) * DD_ + rr + 8] = (uint16_t)(q23 >> 16);
            }
        }
}

// ---------------- kernels ----------------

// seed: split K -> slot1 (row-major + transposed), z0 -> anchor 0
__global__ void __launch_bounds__(512) k_seed(const float* __restrict__ K,
                                              const float* __restrict__ z0) {
    int i = blockIdx.x * blockDim.x + threadIdx.x;
    if (i < NDD) {
        float v = K[i];
        uint32_t p = bf16x2_pack(v, v);
        uint16_t hp = (uint16_t)p;
        uint16_t lp = (uint16_t)bf16x2_pack(v - bf16_lo_f(p), 0.0f);
        int r = i >> 9, cc = i & 511;
        gPh[i] = hp;  gPl[i] = lp;
        gPTh[(size_t)cc * DD_ + r] = hp;
        gPTl[(size_t)cc * DD_ + r] = lp;
    } else {
        int j = i - NDD;
        float v = z0[j];
        uint32_t p = bf16x2_pack(v, v);
        gAh[j] = (uint16_t)p;
        gAl[j] = (uint16_t)bf16x2_pack(v - bf16_lo_f(p), 0.0f);
    }
}

// powers doubling: for z in [0,base): P_{base+z+1} = P_base @ P_{z+1}
__global__ void __launch_bounds__(512, 1) k_power(int base) {
    int z = blockIdx.z;
    int dst = base + z + 1;
    gemm_sk(Ph(base), Pl(base), PTh(z + 1), PTl(z + 1),
            Ph(dst), Pl(dst), PTh(dst), PTl(dst),
            blockIdx.y * 64, blockIdx.x * 64);
}

// round7: z0: K^64 = K^32 @ K^32 (slot 33);  z1: a1 = a0 @ K^32
__global__ void __launch_bounds__(512, 1) k_round7() {
    int m0 = blockIdx.y * 64, n0 = blockIdx.x * 64;
    if (blockIdx.z == 0) {
        gemm_sk(Ph(32), Pl(32), PTh(32), PTl(32),
                Ph(33), Pl(33), PTh(33), PTl(33), m0, n0);
    } else {
        if (m0 >= BB) return;
        gemm_sk(gAh, gAl, PTh(32), PTl(32),
                gAh + NBD, gAl + NBD, nullptr, nullptr, m0, n0);
    }
}

// round8: z0: K^128 = K^64 @ K^64 (slot 34); z1: a2 = a0 @ K^64; z2: a3 = a1 @ K^64
__global__ void __launch_bounds__(512, 1) k_round8() {
    int m0 = blockIdx.y * 64, n0 = blockIdx.x * 64;
    if (blockIdx.z == 0) {
        gemm_sk(Ph(33), Pl(33), PTh(33), PTl(33),
                Ph(34), Pl(34), PTh(34), PTl(34), m0, n0);
    } else {
        if (m0 >= BB) return;
        int i = blockIdx.z - 1;  // 0 or 1
        gemm_sk(gAh + (size_t)i * NBD, gAl + (size_t)i * NBD, PTh(33), PTl(33),
                gAh + (size_t)(i + 2) * NBD, gAl + (size_t)(i + 2) * NBD,
                nullptr, nullptr, m0, n0);
    }
}

// round9: a_{4+z} = a_z @ K^128, z = 0..3
__global__ void __launch_bounds__(512, 1) k_round9() {
    int z = blockIdx.z;
    gemm_sk(gAh + (size_t)z * NBD, gAl + (size_t)z * NBD, PTh(34), PTl(34),
            gAh + (size_t)(z + 4) * NBD, gAl + (size_t)(z + 4) * NBD,
            nullptr, nullptr, blockIdx.y * 64, blockIdx.x * 64);
}

// fine: out[:, t, :] = a_{t>>5} @ K^{(t&31)+1}, all 256 t in parallel (128x128 tiles)
__global__ void __launch_bounds__(256, 2) k_fine(float* __restrict__ out) {
    int t = blockIdx.z;
    gemm_fine(gAh + (size_t)(t >> 5) * NBD, gAl + (size_t)(t >> 5) * NBD,
              PTh((t & 31) + 1), PTl((t & 31) + 1),
              out + (size_t)t * DD_, (size_t)TT * DD_,
              blockIdx.y * 128, blockIdx.x * 128);
}

// ---------------- launch ----------------
extern "C" void kernel_launch(void* const* d_in, const int* in_sizes, int n_in,
                              void* d_out, int out_size) {
    const float* z0 = (const float*)d_in[0];
    const float* K  = (const float*)d_in[1];
    float* out = (float*)d_out;

    cudaFuncSetAttribute(k_power,  cudaFuncAttributeMaxDynamicSharedMemorySize, SMEM_ALL);
    cudaFuncSetAttribute(k_round7, cudaFuncAttributeMaxDynamicSharedMemorySize, SMEM_ALL);
    cudaFuncSetAttribute(k_round8, cudaFuncAttributeMaxDynamicSharedMemorySize, SMEM_ALL);
    cudaFuncSetAttribute(k_round9, cudaFuncAttributeMaxDynamicSharedMemorySize, SMEM_ALL);
    cudaFuncSetAttribute(k_fine,   cudaFuncAttributeMaxDynamicSharedMemorySize, SMEM_ALL);

    k_seed<<<(NDD + NBD) / 512, 512>>>(K, z0);

    for (int base = 1; base <= 16; base *= 2)
        k_power<<<dim3(8, 8, base), 512, SMEM_ALL>>>(base);

    k_round7<<<dim3(8, 8, 2), 512, SMEM_ALL>>>();
    k_round8<<<dim3(8, 8, 3), 512, SMEM_ALL>>>();
    k_round9<<<dim3(8, 4, 4), 512, SMEM_ALL>>>();

    k_fine<<<dim3(4, 2, 256), 256, SMEM_ALL>>>(out);
}

// round 15
// speedup vs baseline: 1.0966x; 1.0470x over previous
#include <cuda_runtime.h>
#include <cuda_bf16.h>
#include <cstdint>

// ---------------- problem constants ----------------
#define BB   256
#define DD_  512
#define TT   256
#define NDD  (DD_ * DD_)     // 262144
#define NBD  (BB * DD_)      // 131072

#define KC   32              // k per stage
#define NSTG (DD_ / KC)      // 16 stages
#define THREADS 256

#define STG_BYTES(TMv, TNv) (2 * (TMv) * 64 + 2 * (TNv) * 64)
#define SMEM_SMALL (6 * STG_BYTES(64, 64))      // 98304 (NBUF=6)
#define SMEM_BIG   (3 * STG_BYTES(128, 128))    // 98304 (NBUF=3)

// ---------------- pre-split bf16 hi/lo global matrices ----------------
static __device__ __align__(16) uint16_t gPh [34 * NDD];
static __device__ __align__(16) uint16_t gPl [34 * NDD];
static __device__ __align__(16) uint16_t gPTh[34 * NDD];
static __device__ __align__(16) uint16_t gPTl[34 * NDD];
static __device__ __align__(16) uint16_t gAh [8 * NBD];
static __device__ __align__(16) uint16_t gAl [8 * NBD];

static __device__ __forceinline__ uint16_t* Ph (int j) { return gPh  + (size_t)(j - 1) * NDD; }
static __device__ __forceinline__ uint16_t* Pl (int j) { return gPl  + (size_t)(j - 1) * NDD; }
static __device__ __forceinline__ uint16_t* PTh(int j) { return gPTh + (size_t)(j - 1) * NDD; }
static __device__ __forceinline__ uint16_t* PTl(int j) { return gPTl + (size_t)(j - 1) * NDD; }

// ---------------- helpers ----------------
static __device__ __forceinline__ uint32_t smem_u32(const void* p) {
    uint32_t a;
    asm("{ .reg .u64 t; cvta.to.shared.u64 t, %1; cvt.u32.u64 %0, t; }" : "=r"(a) : "l"(p));
    return a;
}
static __device__ __forceinline__ uint32_t bf16x2_pack(float x0, float x1) {
    uint32_t d;
    asm("cvt.rn.bf16x2.f32 %0, %2, %1;" : "=r"(d) : "f"(x0), "f"(x1));
    return d;
}
static __device__ __forceinline__ float bf16_lo_f(uint32_t u) { return __uint_as_float(u << 16); }
static __device__ __forceinline__ float bf16_hi_f(uint32_t u) { return __uint_as_float(u & 0xFFFF0000u); }

// swizzle for 64B rows: XOR 16B-chunk bits [5:4] with row bits [2:1]
static __device__ __forceinline__ uint32_t swz64(uint32_t off) {
    return off ^ ((off >> 3) & 0x30u);
}

#define LDSM4(r0, r1, r2, r3, addr) \
    asm volatile("ldmatrix.sync.aligned.m8n8.x4.shared.b16 {%0,%1,%2,%3}, [%4];" \
                 : "=r"(r0), "=r"(r1), "=r"(r2), "=r"(r3) : "r"(addr))

#define MMA16816(c, a, b0, b1) \
    asm volatile("mma.sync.aligned.m16n8k16.row.col.f32.bf16.bf16.f32 " \
                 "{%0,%1,%2,%3}, {%4,%5,%6,%7}, {%8,%9}, {%0,%1,%2,%3};" \
                 : "+f"((c)[0]), "+f"((c)[1]), "+f"((c)[2]), "+f"((c)[3]) \
                 : "r"((a)[0]), "r"((a)[1]), "r"((a)[2]), "r"((a)[3]), \
                   "r"(b0), "r"(b1))

#define CP16(dst, src) \
    asm volatile("cp.async.cg.shared.global [%0], [%1], 16;" :: "r"(dst), "l"(src))
#define CPCOMMIT() asm volatile("cp.async.commit_group;" ::: "memory")
#define CPWAITN(n) asm volatile("cp.async.wait_group %0;" :: "n"(n) : "memory")

// ---------------- TMv x TNv x 512 split-bf16 HMMA GEMM tile ----------------
// C[m][n] = sum_k (Ah+Al)[m][k]*(Bh+Bl)[n][k], lo*lo dropped. Outputs nullable:
// fp32 C (stride cs); bf16 hi/lo row-major Ch/Cl (stride 512); transposed CTh/CTl.
// NB = smem stage buffers, DP = prefetch distance (NB >= DP+1).
template<int TMv, int TNv, int THR, int NB, int DP>
static __device__ __forceinline__ void gemmt(
        const uint16_t* __restrict__ Ah, const uint16_t* __restrict__ Al,
        const uint16_t* __restrict__ Bh, const uint16_t* __restrict__ Bl,
        float* __restrict__ C, size_t cs,
        uint16_t* __restrict__ Ch, uint16_t* __restrict__ Cl,
        uint16_t* __restrict__ CTh, uint16_t* __restrict__ CTl,
        int m0, int n0) {
    static_assert(NB >= DP + 1, "buffer reuse hazard");
    constexpr int NWM = TMv / 32;
    constexpr int NWN = (THR / 32) / NWM;
    constexpr int WN  = TNv / NWN;
    constexpr int NF  = WN / 8;
    constexpr int NQ  = WN / 16;
    constexpr int AMB = TMv * 64;
    constexpr int BMB = TNv * 64;
    constexpr int STG = 2 * AMB + 2 * BMB;

    extern __shared__ char smem[];
    const uint32_t sb = smem_u32(smem);
    const int tid = threadIdx.x;
    const int wid = tid >> 5, l = tid & 31;
    const int wm = (wid / NWN) * 32;
    const int wn = (wid % NWN) * WN;

    float c[2][NF][4];
#pragma unroll
    for (int i = 0; i < 2; ++i)
#pragma unroll
        for (int j = 0; j < NF; ++j)
#pragma unroll
            for (int q = 0; q < 4; ++q) c[i][j][q] = 0.0f;

    const uint32_t a_row = (uint32_t)(wm + (l & 15));
    const uint32_t a_ch  = (uint32_t)(l >> 4);
    const uint32_t b_row = (uint32_t)(wn + (l & 7) + ((l & 16) >> 1));
    const uint32_t b_ch  = (uint32_t)((l >> 3) & 1);

    auto issue = [&](int s) {
        const uint32_t bufb = sb + (uint32_t)(s % NB) * STG;
        const int ko = s * KC;
#pragma unroll
        for (int i = tid; i < TMv * 4; i += THR) {
            const int row = i >> 2, ch = i & 3;
            const uint32_t d = bufb + swz64((uint32_t)(row * 64 + ch * 16));
            const size_t g = (size_t)(m0 + row) * DD_ + ko + ch * 8;
            CP16(d,       Ah + g);
            CP16(d + AMB, Al + g);
        }
#pragma unroll
        for (int i = tid; i < TNv * 4; i += THR) {
            const int row = i >> 2, ch = i & 3;
            const uint32_t d = bufb + 2 * AMB + swz64((uint32_t)(row * 64 + ch * 16));
            const size_t g = (size_t)(n0 + row) * DD_ + ko + ch * 8;
            CP16(d,       Bh + g);
            CP16(d + BMB, Bl + g);
        }
    };

#pragma unroll
    for (int s = 0; s < DP; ++s) { issue(s); CPCOMMIT(); }

    for (int s = 0; s < NSTG; ++s) {
        CPWAITN(DP - 1);
        __syncthreads();

        const uint32_t base = sb + (uint32_t)(s % NB) * STG;
        const uint32_t sA  = base;
        const uint32_t sAl = base + AMB;
        const uint32_t sB  = base + 2 * AMB;
        const uint32_t sBl = base + 2 * AMB + BMB;

#pragma unroll
        for (int kk = 0; kk < 2; ++kk) {
            uint32_t ah[2][4], al[2][4], bh[NQ][4], bl[NQ][4];
            const uint32_t ach = (uint32_t)(2 * kk) + a_ch;
            const uint32_t bch = (uint32_t)(2 * kk) + b_ch;
#pragma unroll
            for (int mf = 0; mf < 2; ++mf) {
                const uint32_t off = swz64((a_row + mf * 16) * 64 + ach * 16);
                LDSM4(ah[mf][0], ah[mf][1], ah[mf][2], ah[mf][3], sA + off);
                LDSM4(al[mf][0], al[mf][1], al[mf][2], al[mf][3], sAl + off);
            }
#pragma unroll
            for (int q = 0; q < NQ; ++q) {
                const uint32_t off = swz64((b_row + q * 16) * 64 + bch * 16);
                LDSM4(bh[q][0], bh[q][1], bh[q][2], bh[q][3], sB + off);
                LDSM4(bl[q][0], bl[q][1], bl[q][2], bl[q][3], sBl + off);
            }
#pragma unroll
            for (int mf = 0; mf < 2; ++mf)
#pragma unroll
                for (int nf = 0; nf < NF; ++nf) {
                    const int q = nf >> 1, hh = (nf & 1) * 2;
                    MMA16816(c[mf][nf], ah[mf], bh[q][hh], bh[q][hh + 1]);
                    MMA16816(c[mf][nf], ah[mf], bl[q][hh], bl[q][hh + 1]);
                    MMA16816(c[mf][nf], al[mf], bh[q][hh], bh[q][hh + 1]);
                }
        }
        if (s + DP < NSTG) issue(s + DP);
        CPCOMMIT();
    }

    // ---------------- epilogue ----------------
    const int row0 = m0 + wm + (l >> 2);
    const int col0 = n0 + wn + 2 * (l & 3);
#pragma unroll
    for (int mf = 0; mf < 2; ++mf)
#pragma unroll
        for (int nf = 0; nf < NF; ++nf) {
            const int rr = row0 + mf * 16;
            const int cc = col0 + nf * 8;
            const float v0 = c[mf][nf][0], v1 = c[mf][nf][1];
            const float v2 = c[mf][nf][2], v3 = c[mf][nf][3];
            if (C) {
                *(float2*)(C + (size_t)rr * cs + cc)       = make_float2(v0, v1);
                *(float2*)(C + (size_t)(rr + 8) * cs + cc) = make_float2(v2, v3);
            }
            if (Ch) {
                uint32_t p01 = bf16x2_pack(v0, v1);
                uint32_t p23 = bf16x2_pack(v2, v3);
                uint32_t q01 = bf16x2_pack(v0 - bf16_lo_f(p01), v1 - bf16_hi_f(p01));
                uint32_t q23 = bf16x2_pack(v2 - bf16_lo_f(p23), v3 - bf16_hi_f(p23));
                *(uint32_t*)(Ch + (size_t)rr * DD_ + cc)       = p01;
                *(uint32_t*)(Cl + (size_t)rr * DD_ + cc)       = q01;
                *(uint32_t*)(Ch + (size_t)(rr + 8) * DD_ + cc) = p23;
                *(uint32_t*)(Cl + (size_t)(rr + 8) * DD_ + cc) = q23;
                if (CTh) {
                    CTh[(size_t)cc * DD_ + rr]           = (uint16_t)p01;
                    CTh[(size_t)(cc + 1) * DD_ + rr]     = (uint16_t)(p01 >> 16);
                    CTh[(size_t)cc * DD_ + rr + 8]       = (uint16_t)p23;
                    CTh[(size_t)(cc + 1) * DD_ + rr + 8] = (uint16_t)(p23 >> 16);
                    CTl[(size_t)cc * DD_ + rr]           = (uint16_t)q01;
                    CTl[(size_t)(cc + 1) * DD_ + rr]     = (uint16_t)(q01 >> 16);
                    CTl[(size_t)cc * DD_ + rr + 8]       = (uint16_t)q23;
                    CTl[(size_t)(cc + 1) * DD_ + rr + 8] = (uint16_t)(q23 >> 16);
                }
            }
        }
}

// ---------------- kernels ----------------

// seed: split K -> slot1 (row-major + transposed), z0 -> anchor 0
__global__ void __launch_bounds__(512) k_seed(const float* __restrict__ K,
                                              const float* __restrict__ z0) {
    int i = blockIdx.x * blockDim.x + threadIdx.x;
    if (i < NDD) {
        float v = K[i];
        uint32_t p = bf16x2_pack(v, v);
        uint16_t hp = (uint16_t)p;
        uint16_t lp = (uint16_t)bf16x2_pack(v - bf16_lo_f(p), 0.0f);
        int r = i >> 9, cc = i & 511;
        gPh[i] = hp;  gPl[i] = lp;
        gPTh[(size_t)cc * DD_ + r] = hp;
        gPTl[(size_t)cc * DD_ + r] = lp;
    } else {
        int j = i - NDD;
        float v = z0[j];
        uint32_t p = bf16x2_pack(v, v);
        gAh[j] = (uint16_t)p;
        gAl[j] = (uint16_t)bf16x2_pack(v - bf16_lo_f(p), 0.0f);
    }
}

// small sequential rounds: 64x64 tiles, deep prefetch (NBUF=6, D=5)
#define TS 64
#define SMALL_GEMM gemmt<TS, TS, THREADS, 6, 5>
// big rounds / fine: 128x128 tiles (NBUF=3, D=2)
#define BIG_GEMM   gemmt<128, 128, THREADS, 3, 2>

// powers doubling (small bases 1,2,4): P_{base+z+1} = P_base @ P_{z+1}
__global__ void __launch_bounds__(THREADS, 2) k_power(int base) {
    int z = blockIdx.z;
    int dst = base + z + 1;
    SMALL_GEMM(Ph(base), Pl(base), PTh(z + 1), PTl(z + 1),
               nullptr, 0, Ph(dst), Pl(dst), PTh(dst), PTl(dst),
               blockIdx.y * TS, blockIdx.x * TS);
}

// powers doubling (big bases 8,16): 128x128 tiles, single wave
__global__ void __launch_bounds__(THREADS, 2) k_power_big(int base) {
    int z = blockIdx.z;
    int dst = base + z + 1;
    BIG_GEMM(Ph(base), Pl(base), PTh(z + 1), PTl(z + 1),
             nullptr, 0, Ph(dst), Pl(dst), PTh(dst), PTl(dst),
             blockIdx.y * 128, blockIdx.x * 128);
}

// round7: z0: K^64 = K^32 @ K^32 (slot 33);  z1: a1 = a0 @ K^32
__global__ void __launch_bounds__(THREADS, 2) k_round7() {
    int m0 = blockIdx.y * TS, n0 = blockIdx.x * TS;
    if (blockIdx.z == 0) {
        SMALL_GEMM(Ph(32), Pl(32), PTh(32), PTl(32),
                   nullptr, 0, Ph(33), Pl(33), PTh(33), PTl(33), m0, n0);
    } else {
        if (m0 >= BB) return;
        SMALL_GEMM(gAh, gAl, PTh(32), PTl(32),
                   nullptr, 0, gAh + NBD, gAl + NBD, nullptr, nullptr, m0, n0);
    }
}

// round8: z0: K^128 = K^64 @ K^64 (slot 34); z1: a2 = a0 @ K^64; z2: a3 = a1 @ K^64
__global__ void __launch_bounds__(THREADS, 2) k_round8() {
    int m0 = blockIdx.y * TS, n0 = blockIdx.x * TS;
    if (blockIdx.z == 0) {
        SMALL_GEMM(Ph(33), Pl(33), PTh(33), PTl(33),
                   nullptr, 0, Ph(34), Pl(34), PTh(34), PTl(34), m0, n0);
    } else {
        if (m0 >= BB) return;
        int i = blockIdx.z - 1;  // 0 or 1
        SMALL_GEMM(gAh + (size_t)i * NBD, gAl + (size_t)i * NBD, PTh(33), PTl(33),
                   nullptr, 0, gAh + (size_t)(i + 2) * NBD, gAl + (size_t)(i + 2) * NBD,
                   nullptr, nullptr, m0, n0);
    }
}

// round9: a_{4+z} = a_z @ K^128, z = 0..3
__global__ void __launch_bounds__(THREADS, 2) k_round9() {
    int z = blockIdx.z;
    SMALL_GEMM(gAh + (size_t)z * NBD, gAl + (size_t)z * NBD, PTh(34), PTl(34),
               nullptr, 0, gAh + (size_t)(z + 4) * NBD, gAl + (size_t)(z + 4) * NBD,
               nullptr, nullptr, blockIdx.y * TS, blockIdx.x * TS);
}

// fine: out[:, t, :] = a_{t>>5} @ K^{(t&31)+1}, all 256 t in parallel (128x128 tiles)
__global__ void __launch_bounds__(THREADS, 2) k_fine(float* __restrict__ out) {
    int t = blockIdx.z;
    BIG_GEMM(gAh + (size_t)(t >> 5) * NBD, gAl + (size_t)(t >> 5) * NBD,
             PTh((t & 31) + 1), PTl((t & 31) + 1),
             out + (size_t)t * DD_, (size_t)TT * DD_,
             nullptr, nullptr, nullptr, nullptr,
             blockIdx.y * 128, blockIdx.x * 128);
}

// ---------------- launch ----------------
extern "C" void kernel_launch(void* const* d_in, const int* in_sizes, int n_in,
                              void* d_out, int out_size) {
    const float* z0 = (const float*)d_in[0];
    const float* K  = (const float*)d_in[1];
    float* out = (float*)d_out;

    cudaFuncSetAttribute(k_power,     cudaFuncAttributeMaxDynamicSharedMemorySize, SMEM_SMALL);
    cudaFuncSetAttribute(k_power_big, cudaFuncAttributeMaxDynamicSharedMemorySize, SMEM_BIG);
    cudaFuncSetAttribute(k_round7,    cudaFuncAttributeMaxDynamicSharedMemorySize, SMEM_SMALL);
    cudaFuncSetAttribute(k_round8,    cudaFuncAttributeMaxDynamicSharedMemorySize, SMEM_SMALL);
    cudaFuncSetAttribute(k_round9,    cudaFuncAttributeMaxDynamicSharedMemorySize, SMEM_SMALL);
    cudaFuncSetAttribute(k_fine,      cudaFuncAttributeMaxDynamicSharedMemorySize, SMEM_BIG);

    k_seed<<<(NDD + NBD) / 512, 512>>>(K, z0);

    // small bases: 1 wave of 64x64 tiles each
    for (int base = 1; base <= 4; base *= 2)
        k_power<<<dim3(DD_ / TS, DD_ / TS, base), THREADS, SMEM_SMALL>>>(base);
    // big bases: 1 wave of 128x128 tiles each (128 / 256 CTAs)
    for (int base = 8; base <= 16; base *= 2)
        k_power_big<<<dim3(DD_ / 128, DD_ / 128, base), THREADS, SMEM_BIG>>>(base);

    k_round7<<<dim3(DD_ / TS, DD_ / TS, 2), THREADS, SMEM_SMALL>>>();
    k_round8<<<dim3(DD_ / TS, DD_ / TS, 3), THREADS, SMEM_SMALL>>>();
    k_round9<<<dim3(DD_ / TS, BB / TS, 4), THREADS, SMEM_SMALL>>>();

    k_fine<<<dim3(DD_ / 128, BB / 128, TT), THREADS, SMEM_BIG>>>(out);
}